// round 4
// baseline (speedup 1.0000x reference)
#include <cuda_runtime.h>

#define DD   256
#define NN   8192
#define EE   8191
#define ALPHA 0.2f

// ---------------- scratch (allocation-free __device__ globals) ----------------
__device__ __align__(16) float g_w12[2 * DD];   // w1 = a[0:D]^T W, w2 = a[D:2D]^T W
__device__ __align__(16) float g_Wt[DD * DD];   // W pre-rounded to tf32 (rna)
__device__ __align__(16) float g_Y[NN * DD];    // gathered A matrix (fp32)

__device__ __forceinline__ unsigned f2tf(float f) {
    unsigned r; asm("cvt.rna.tf32.f32 %0, %1;" : "=r"(r) : "f"(f)); return r;
}
__device__ __forceinline__ float tfbits(float f) { return __uint_as_float(f2tf(f)); }
__device__ __forceinline__ float lrelu(float v) { return v > 0.f ? v : ALPHA * v; }
__device__ __forceinline__ unsigned su32(const void* p) {
    return (unsigned)__cvta_generic_to_shared(p);
}
__device__ __forceinline__ float dot4(float4 a, float4 b) {
    return a.x * b.x + a.y * b.y + a.z * b.z + a.w * b.w;
}

#define CP16(d, s) asm volatile("cp.async.ca.shared.global [%0], [%1], 16;" :: "r"(d), "l"(s))

// ---------------- K1: zero Y + convert W->tf32 + w12 vectors --------------------
__global__ __launch_bounds__(256) void k_pre(const float* __restrict__ W,
                                             const float* __restrict__ a) {
    int b = blockIdx.x, t = threadIdx.x;
    if (b < 512) {                       // zero Y: 512 blocks x 1024 float4
        float4* y4 = (float4*)g_Y;
        int base = b * 1024 + t * 4;
        float4 z = make_float4(0.f, 0.f, 0.f, 0.f);
        y4[base + 0] = z; y4[base + 1] = z; y4[base + 2] = z; y4[base + 3] = z;
    } else if (b < 528) {                // W -> tf32(rna): 16 blocks x 1024 float4
        const float4* w4 = (const float4*)W;
        float4* o4 = (float4*)g_Wt;
        int base = (b - 512) * 1024 + t * 4;
#pragma unroll
        for (int j = 0; j < 4; j++) {
            float4 v = w4[base + j];
            v.x = tfbits(v.x); v.y = tfbits(v.y); v.z = tfbits(v.z); v.w = tfbits(v.w);
            o4[base + j] = v;
        }
    } else {                             // w12: 2 blocks, thread t = output index
        int half = b - 528;
        const float* ah = a + half * DD;
        float acc = 0.f;
#pragma unroll 32
        for (int j = 0; j < DD; j++)
            acc += ah[j] * W[j * DD + t];
        g_w12[half * DD + t] = acc;
    }
}

// ---------------- K2: one warp per edge: logit sign + scatter-add into Y --------
// Y[dep] += x[gov];  Y[gov] += coef * x[dep].  Each Y row receives <=2 atomic
// float adds -> commutative -> deterministic across replays.
__global__ __launch_bounds__(256) void k_edge(const float* __restrict__ x,
                                              const int* __restrict__ dep,
                                              const int* __restrict__ gov) {
    int e = blockIdx.x * 8 + (threadIdx.x >> 5);
    int lane = threadIdx.x & 31;
    if (e >= EE) return;
    int g = gov[e], d = dep[e];

    const float4* x4 = (const float4*)x;
    const float4* w4 = (const float4*)g_w12;
    float4 w1a = w4[lane * 2],      w1b = w4[lane * 2 + 1];
    float4 w2a = w4[64 + lane * 2], w2b = w4[64 + lane * 2 + 1];
    float4 xg0 = x4[g * 64 + lane * 2], xg1 = x4[g * 64 + lane * 2 + 1];
    float4 xd0 = x4[d * 64 + lane * 2], xd1 = x4[d * 64 + lane * 2 + 1];

    float s = dot4(xg0, w1a) + dot4(xg1, w1b) + dot4(xd0, w2a) + dot4(xd1, w2b);
#pragma unroll
    for (int o = 16; o; o >>= 1)
        s += __shfl_xor_sync(0xFFFFFFFFu, s, o);
    float coef = (s > 0.f) ? 1.f : (1.f / (float)NN);

    float* Yd = g_Y + d * DD + lane * 8;
    atomicAdd(Yd + 0, xg0.x); atomicAdd(Yd + 1, xg0.y);
    atomicAdd(Yd + 2, xg0.z); atomicAdd(Yd + 3, xg0.w);
    atomicAdd(Yd + 4, xg1.x); atomicAdd(Yd + 5, xg1.y);
    atomicAdd(Yd + 6, xg1.z); atomicAdd(Yd + 7, xg1.w);

    float* Yg = g_Y + g * DD + lane * 8;
    atomicAdd(Yg + 0, coef * xd0.x); atomicAdd(Yg + 1, coef * xd0.y);
    atomicAdd(Yg + 2, coef * xd0.z); atomicAdd(Yg + 3, coef * xd0.w);
    atomicAdd(Yg + 4, coef * xd1.x); atomicAdd(Yg + 5, coef * xd1.y);
    atomicAdd(Yg + 6, coef * xd1.z); atomicAdd(Yg + 7, coef * xd1.w);
}

// ---------------- K3: cp.async 3-stage pipelined tf32 GEMM + leaky relu ---------
// out = lrelu(Y @ Wt^T); BM=128, BN=64, BK=32, 8 warps (2m x 4n), warp 64x16.
#define ASTG (128 * 36)
#define BSTG (64 * 36)

__global__ __launch_bounds__(256, 2) void k_gemm(float* __restrict__ out) {
    extern __shared__ float sm[];
    float* Asm = sm;
    float* Bsm = sm + 3 * ASTG;

    int tid = threadIdx.x;
    int m0 = blockIdx.y * 128;
    int n0 = blockIdx.x * 64;

    // ---- cp.async load mapping: A 4 chunks/thread, B 2 chunks/thread ----
    int arow = tid >> 1, ahalf = tid & 1;
    int brow = tid >> 2, bq = tid & 3;
    const float* gA = g_Y  + (m0 + arow) * DD + ahalf * 16;
    const float* gB = g_Wt + (n0 + brow) * DD + bq * 8;
    unsigned sA = su32(Asm + arow * 36 + ahalf * 16);
    unsigned sB = su32(Bsm + brow * 36 + bq * 8);

#define ISSUE(kt, stg) do {                                                   \
        const float* ga = gA + (kt) * 32;                                     \
        unsigned da = sA + (stg) * ASTG * 4;                                  \
        CP16(da +  0, ga + 0); CP16(da + 16, ga + 4);                         \
        CP16(da + 32, ga + 8); CP16(da + 48, ga + 12);                        \
        const float* gb = gB + (kt) * 32;                                     \
        unsigned db = sB + (stg) * BSTG * 4;                                  \
        CP16(db + 0, gb + 0); CP16(db + 16, gb + 4);                          \
        asm volatile("cp.async.commit_group;" ::: "memory");                  \
    } while (0)

    ISSUE(0, 0);
    ISSUE(1, 1);

    // ---- fragment addressing ----
    int wid = tid >> 5, lane = tid & 31;
    int wm = (wid & 1) * 64;
    int wn = (wid >> 1) * 16;
    int aRow = wm + (lane & 7) + ((lane & 8) ? 8 : 0);
    int aColF = (lane & 16) ? 4 : 0;
    unsigned aB = su32(Asm + aRow * 36 + aColF);
    int bRow = wn + (lane & 7);
    int bColF = (lane & 8) ? 4 : 0;
    unsigned bB = su32(Bsm + bRow * 36 + bColF);

    float acc[4][2][4];
#pragma unroll
    for (int i = 0; i < 4; i++)
#pragma unroll
        for (int j = 0; j < 2; j++)
#pragma unroll
            for (int v = 0; v < 4; v++) acc[i][j][v] = 0.f;

#pragma unroll 1
    for (int kt = 0; kt < 8; kt++) {
        if (kt < 7) asm volatile("cp.async.wait_group 1;" ::: "memory");
        else        asm volatile("cp.async.wait_group 0;" ::: "memory");
        __syncthreads();
        if (kt + 2 < 8) {
            int ns = (kt + 2) % 3;      // buffer last read in iter kt-1: free
            ISSUE(kt + 2, ns);
        }
        int stg = kt % 3;
        unsigned aS = aB + stg * ASTG * 4;
        unsigned bS = bB + stg * BSTG * 4;
#pragma unroll
        for (int ks = 0; ks < 4; ks++) {
            int k = ks * 8;
            unsigned af[4][4], bf[2][2];
#pragma unroll
            for (int mf = 0; mf < 4; mf++)
                asm volatile("ldmatrix.sync.aligned.m8n8.x4.shared.b16 {%0,%1,%2,%3}, [%4];"
                    : "=r"(af[mf][0]), "=r"(af[mf][1]), "=r"(af[mf][2]), "=r"(af[mf][3])
                    : "r"(aS + (unsigned)((mf * 576 + k) * 4)));
#pragma unroll
            for (int nf = 0; nf < 2; nf++)
                asm volatile("ldmatrix.sync.aligned.m8n8.x2.shared.b16 {%0,%1}, [%2];"
                    : "=r"(bf[nf][0]), "=r"(bf[nf][1])
                    : "r"(bS + (unsigned)((nf * 288 + k) * 4)));
#pragma unroll
            for (int mf = 0; mf < 4; mf++)
#pragma unroll
                for (int nf = 0; nf < 2; nf++)
                    asm volatile(
                        "mma.sync.aligned.m16n8k8.row.col.f32.tf32.tf32.f32 "
                        "{%0,%1,%2,%3}, {%4,%5,%6,%7}, {%8,%9}, {%0,%1,%2,%3};"
                        : "+f"(acc[mf][nf][0]), "+f"(acc[mf][nf][1]),
                          "+f"(acc[mf][nf][2]), "+f"(acc[mf][nf][3])
                        : "r"(af[mf][0]), "r"(af[mf][1]), "r"(af[mf][2]), "r"(af[mf][3]),
                          "r"(bf[nf][0]), "r"(bf[nf][1]));
        }
    }

    // ---- epilogue ----
    int er = m0 + wm + (lane >> 2);
    int ec = n0 + wn + (lane & 3) * 2;
#pragma unroll
    for (int mf = 0; mf < 4; mf++) {
#pragma unroll
        for (int nf = 0; nf < 2; nf++) {
            float2 v0, v1;
            v0.x = lrelu(acc[mf][nf][0]); v0.y = lrelu(acc[mf][nf][1]);
            v1.x = lrelu(acc[mf][nf][2]); v1.y = lrelu(acc[mf][nf][3]);
            *(float2*)&out[(er + mf * 16) * DD + ec + nf * 8]     = v0;
            *(float2*)&out[(er + mf * 16 + 8) * DD + ec + nf * 8] = v1;
        }
    }
}

// ---------------- launch ---------------------------------------------------------
extern "C" void kernel_launch(void* const* d_in, const int* in_sizes, int n_in,
                              void* d_out, int out_size) {
    const float* x   = (const float*)d_in[0];
    const float* W   = (const float*)d_in[1];
    const float* a   = (const float*)d_in[2];
    const int*   dep = (const int*)d_in[3];
    const int*   gov = (const int*)d_in[4];
    float* out = (float*)d_out;

    int smem = 3 * (ASTG + BSTG) * 4;   // 82,944 B
    cudaFuncSetAttribute(k_gemm, cudaFuncAttributeMaxDynamicSharedMemorySize, smem);

    k_pre <<<530, 256>>>(W, a);
    k_edge<<<1024, 256>>>(x, dep, gov);
    k_gemm<<<dim3(4, 64), 256, smem>>>(out);
}

// round 5
// speedup vs baseline: 2.2569x; 2.2569x over previous
#include <cuda_runtime.h>

#define DD   256
#define NN   8192
#define EE   8191
#define ALPHA 0.2f

// ---------------- scratch (allocation-free __device__ globals, zero-init) -------
// per-output-row gather tables: out_row r = lrelu((cA*x[sA] + cB*x[sB]) @ W^T)
__device__ float g_w12[2 * DD];
__device__ float g_cA[NN];
__device__ float g_cB[NN];
__device__ int   g_sA[NN];
__device__ int   g_sB[NN];

__device__ __forceinline__ unsigned f2tf(float f) {
    unsigned r; asm("cvt.rna.tf32.f32 %0, %1;" : "=r"(r) : "f"(f)); return r;
}
__device__ __forceinline__ float tfbits(float f) { return __uint_as_float(f2tf(f)); }
__device__ __forceinline__ float lrelu(float v) { return v > 0.f ? v : ALPHA * v; }
__device__ __forceinline__ unsigned su32(const void* p) {
    return (unsigned)__cvta_generic_to_shared(p);
}
__device__ __forceinline__ float dot4(float4 a, float4 b) {
    return a.x * b.x + a.y * b.y + a.z * b.z + a.w * b.w;
}

// ---------------- K1: w1 = a[0:D]^T W, w2 = a[D:2D]^T W --------------------------
// 16 blocks: block b -> half (b>>3), 32-col slice ((b&7)*32). 8 warps x 32 rows,
// lane = column within slice (coalesced 128B row segments). smem reduce.
__global__ __launch_bounds__(256) void k_w12(const float* __restrict__ W,
                                             const float* __restrict__ a) {
    __shared__ float part[8][32];
    int b = blockIdx.x, tid = threadIdx.x;
    int half = b >> 3, c0 = (b & 7) * 32;
    int w = tid >> 5, l = tid & 31;
    const float* ah = a + half * DD;
    float p = 0.f;
#pragma unroll 8
    for (int i = 0; i < 32; i++) {
        int j = w * 32 + i;
        p += ah[j] * W[j * DD + c0 + l];
    }
    part[w][l] = p;
    __syncthreads();
    if (tid < 32) {
        float s = 0.f;
#pragma unroll
        for (int r = 0; r < 8; r++) s += part[r][tid];
        g_w12[half * DD + c0 + tid] = s;
    }
}

// ---------------- K2: one warp per edge: logit sign -> gather tables ------------
__global__ __launch_bounds__(256) void k_edge(const float* __restrict__ x,
                                              const int* __restrict__ dep,
                                              const int* __restrict__ gov) {
    int e = blockIdx.x * 8 + (threadIdx.x >> 5);
    int lane = threadIdx.x & 31;
    if (e >= EE) return;
    int g = gov[e], d = dep[e];

    const float4* x4 = (const float4*)x;
    const float4* w4 = (const float4*)g_w12;
    float4 w1a = w4[lane * 2],      w1b = w4[lane * 2 + 1];
    float4 w2a = w4[64 + lane * 2], w2b = w4[64 + lane * 2 + 1];
    float4 xg0 = x4[g * 64 + lane * 2], xg1 = x4[g * 64 + lane * 2 + 1];
    float4 xd0 = x4[d * 64 + lane * 2], xd1 = x4[d * 64 + lane * 2 + 1];

    float s = dot4(xg0, w1a) + dot4(xg1, w1b) + dot4(xd0, w2a) + dot4(xd1, w2b);
#pragma unroll
    for (int o = 16; o; o >>= 1)
        s += __shfl_xor_sync(0xFFFFFFFFu, s, o);
    if (lane == 0) {
        float coef = (s > 0.f) ? 1.f : (1.f / (float)NN);
        g_cA[d] = 1.f;  g_sA[d] = g;   // h[dep]  = Hx[gov]
        g_cB[g] = coef; g_sB[g] = d;   // h[gov] += coef * Hx[dep]
    }
}

// ---------------- K3: double-buffered fused-gather tf32 GEMM + leaky relu -------
// BM=128, BN=128, BK=32; 512 thr, 16 warps 4(m) x 4(n), warp tile 32x32.
#define TSTG (128 * 36)

__global__ __launch_bounds__(512, 1) void k_gemm(
    const float* __restrict__ x, const float* __restrict__ W,
    float* __restrict__ out)
{
    extern __shared__ float sm[];
    float* Asm = sm;              // [2][128*36]
    float* Bsm = sm + 2 * TSTG;   // [2][128*36]

    int tid = threadIdx.x;
    int m0 = blockIdx.y * 128;
    int n0 = blockIdx.x * 128;

    // ---- load mapping: thread -> row (tid>>2), quarter slab (tid&3), 2 f4 each --
    int arow = tid >> 2;
    int aq   = tid & 3;
    int row  = m0 + arow;
    float cA = g_cA[row], cB = g_cB[row];
    int   sA = g_sA[row], sB = g_sB[row];

    const float4* x4 = (const float4*)x;
    const float4* W4 = (const float4*)W;
    int aOff = sA * 64 + aq * 2;
    int bOff = sB * 64 + aq * 2;
    int wOff = (n0 + arow) * 64 + aq * 2;
    int st0  = arow * 36 + aq * 8;

    float4 rg[2], rb[2], rw[2];
#pragma unroll
    for (int j = 0; j < 2; j++) { rg[j] = x4[aOff + j]; rb[j] = x4[bOff + j]; rw[j] = W4[wOff + j]; }

#define STORE_TILE(buf) do {                                                  \
        float* Ad = Asm + (buf) * TSTG + st0;                                 \
        float* Bd = Bsm + (buf) * TSTG + st0;                                 \
        _Pragma("unroll")                                                     \
        for (int j = 0; j < 2; j++) {                                         \
            Ad[j*4+0] = tfbits(cA * rg[j].x + cB * rb[j].x);                  \
            Ad[j*4+1] = tfbits(cA * rg[j].y + cB * rb[j].y);                  \
            Ad[j*4+2] = tfbits(cA * rg[j].z + cB * rb[j].z);                  \
            Ad[j*4+3] = tfbits(cA * rg[j].w + cB * rb[j].w);                  \
            Bd[j*4+0] = tfbits(rw[j].x);                                      \
            Bd[j*4+1] = tfbits(rw[j].y);                                      \
            Bd[j*4+2] = tfbits(rw[j].z);                                      \
            Bd[j*4+3] = tfbits(rw[j].w);                                      \
        }                                                                     \
    } while (0)

    STORE_TILE(0);

    // ---- fragment addressing: 16 warps 4(m) x 4(n), warp tile 32x32 ----
    int wid = tid >> 5, lane = tid & 31;
    int wm  = (wid & 3) * 32;
    int wn  = (wid >> 2) * 32;
    int aRow = wm + (lane & 7) + ((lane & 8) ? 8 : 0);
    int aColF = (lane & 16) ? 4 : 0;
    unsigned aB = su32(Asm + aRow * 36 + aColF);
    int bRow = wn + (lane & 7);
    int bColF = (lane & 8) ? 4 : 0;
    unsigned bB = su32(Bsm + bRow * 36 + bColF);

    float acc[2][4][4];
#pragma unroll
    for (int i = 0; i < 2; i++)
#pragma unroll
        for (int j = 0; j < 4; j++)
#pragma unroll
            for (int v = 0; v < 4; v++) acc[i][j][v] = 0.f;

    __syncthreads();

#pragma unroll 1
    for (int kt = 0; kt < 8; kt++) {
        if (kt < 7) {                    // prefetch next k-slab (hidden under MMAs)
            int kq = (kt + 1) * 8;
#pragma unroll
            for (int j = 0; j < 2; j++) {
                rg[j] = x4[aOff + kq + j];
                rb[j] = x4[bOff + kq + j];
                rw[j] = W4[wOff + kq + j];
            }
        }
        int buf = kt & 1;
        unsigned aS = aB + buf * TSTG * 4;
        unsigned bS = bB + buf * TSTG * 4;
#pragma unroll
        for (int ks = 0; ks < 4; ks++) {
            int k = ks * 8;
            unsigned af[2][4], bf[4][2];
#pragma unroll
            for (int mf = 0; mf < 2; mf++)
                asm volatile("ldmatrix.sync.aligned.m8n8.x4.shared.b16 {%0,%1,%2,%3}, [%4];"
                    : "=r"(af[mf][0]), "=r"(af[mf][1]), "=r"(af[mf][2]), "=r"(af[mf][3])
                    : "r"(aS + (unsigned)((mf * 576 + k) * 4)));
#pragma unroll
            for (int nf = 0; nf < 4; nf++)
                asm volatile("ldmatrix.sync.aligned.m8n8.x2.shared.b16 {%0,%1}, [%2];"
                    : "=r"(bf[nf][0]), "=r"(bf[nf][1])
                    : "r"(bS + (unsigned)((nf * 288 + k) * 4)));
#pragma unroll
            for (int mf = 0; mf < 2; mf++)
#pragma unroll
                for (int nf = 0; nf < 4; nf++)
                    asm volatile(
                        "mma.sync.aligned.m16n8k8.row.col.f32.tf32.tf32.f32 "
                        "{%0,%1,%2,%3}, {%4,%5,%6,%7}, {%8,%9}, {%0,%1,%2,%3};"
                        : "+f"(acc[mf][nf][0]), "+f"(acc[mf][nf][1]),
                          "+f"(acc[mf][nf][2]), "+f"(acc[mf][nf][3])
                        : "r"(af[mf][0]), "r"(af[mf][1]), "r"(af[mf][2]), "r"(af[mf][3]),
                          "r"(bf[nf][0]), "r"(bf[nf][1]));
        }
        if (kt < 7) {
            STORE_TILE(1 - buf);         // opposite buffer: no pre-store sync
            __syncthreads();
        }
    }

    // ---- epilogue: leaky relu, float2 stores ----
    int er = m0 + wm + (lane >> 2);
    int ec = n0 + wn + (lane & 3) * 2;
#pragma unroll
    for (int mf = 0; mf < 2; mf++) {
#pragma unroll
        for (int nf = 0; nf < 4; nf++) {
            float2 v0, v1;
            v0.x = lrelu(acc[mf][nf][0]); v0.y = lrelu(acc[mf][nf][1]);
            v1.x = lrelu(acc[mf][nf][2]); v1.y = lrelu(acc[mf][nf][3]);
            *(float2*)&out[(er + mf * 16) * DD + ec + nf * 8]     = v0;
            *(float2*)&out[(er + mf * 16 + 8) * DD + ec + nf * 8] = v1;
        }
    }
}

// ---------------- launch ---------------------------------------------------------
extern "C" void kernel_launch(void* const* d_in, const int* in_sizes, int n_in,
                              void* d_out, int out_size) {
    const float* x   = (const float*)d_in[0];
    const float* W   = (const float*)d_in[1];
    const float* a   = (const float*)d_in[2];
    const int*   dep = (const int*)d_in[3];
    const int*   gov = (const int*)d_in[4];
    float* out = (float*)d_out;

    int smem = 4 * TSTG * 4;   // 73,728 B (2 bufs x (A+B))
    cudaFuncSetAttribute(k_gemm, cudaFuncAttributeMaxDynamicSharedMemorySize, smem);

    k_w12 <<<16, 256>>>(W, a);
    k_edge<<<1024, 256>>>(x, dep, gov);
    k_gemm<<<dim3(2, 64), 512, smem>>>(x, W, out);
}